// round 10
// baseline (speedup 1.0000x reference)
#include <cuda_runtime.h>
#include <math_constants.h>

// Per-(batch,cell) sums: index == blockIdx.x. Zero-init at module load.
__device__ float g_cells[128 * 4 * 4];
__device__ unsigned int g_done = 0;   // ticket counter; reset by last block

// ---------------------------------------------------------------------------
// Fused kernel: 2048 blocks x 256 threads, one block per (batch, grid cell).
// Phase 1 (all blocks): privately sum own 128x128 cell, write g_cells[bid].
// Phase 2 (last block only, threadfence-reduction pattern): threads 0..127
// each run the window-sum + argmax for one batch and write float (row,col).
// Mean's /16384 scale skipped: uniform positive factor, argmax-invariant.
// ---------------------------------------------------------------------------
__global__ __launch_bounds__(256) void region_selector_fused(
    const float* __restrict__ x, float* __restrict__ out)
{
    const int bid   = blockIdx.x;      // batch*16 + gr*4 + gc
    const int batch = bid >> 4;
    const int cell  = bid & 15;
    const int gr    = cell >> 2;
    const int gc    = cell & 3;

    const int t  = threadIdx.x;        // 0..255
    const int c4 = t & 31;             // float4 col within 128-float cell row
    const int r0 = t >> 5;             // 0..7, rows r0 + 8i

    const float4* __restrict__ p =
        reinterpret_cast<const float4*>(x) + (size_t)batch * 65536;
    const int cellbase = gr * (128 * 128) + gc * 32;   // float4 units

    float s = 0.0f;
    #pragma unroll
    for (int i = 0; i < 16; i++) {
        // Streaming load (evict-first): data is touched exactly once.
        const float4 v = __ldcs(&p[cellbase + (r0 + 8 * i) * 128 + c4]);
        s += (v.x + v.y) + (v.z + v.w);
    }

    #pragma unroll
    for (int o = 16; o > 0; o >>= 1)
        s += __shfl_xor_sync(0xffffffffu, s, o);

    __shared__ float ws[8];
    __shared__ bool  is_last;
    if ((t & 31) == 0) ws[t >> 5] = s;
    __syncthreads();

    if (t == 0) {
        const float tot = (ws[0] + ws[1]) + (ws[2] + ws[3])
                        + (ws[4] + ws[5]) + (ws[6] + ws[7]);
        g_cells[bid] = tot;
        __threadfence();                       // publish before ticket bump
        const unsigned int ticket = atomicAdd(&g_done, 1u);
        is_last = (ticket == gridDim.x - 1);   // all g_cells now visible
    }
    __syncthreads();

    if (is_last) {
        if (t < 128) {
            const int b = t;                   // one batch per thread
            float cells[16];
            #pragma unroll
            for (int i = 0; i < 16; i++) cells[i] = g_cells[b * 16 + i];

            float best = -CUDART_INF_F;
            int   bi   = 0;
            #pragma unroll
            for (int r = 0; r < 2; r++) {
                #pragma unroll
                for (int c = 0; c < 2; c++) {
                    float w = 0.0f;
                    #pragma unroll
                    for (int dr = 0; dr < 3; dr++)
                        #pragma unroll
                        for (int dc = 0; dc < 3; dc++)
                            w += cells[(r + dr) * 4 + (c + dc)];
                    if (w > best) { best = w; bi = r * 2 + c; }  // first-hit
                }
            }
            out[b * 2 + 0] = (float)(bi >> 1);  // row (float output dtype)
            out[b * 2 + 1] = (float)(bi & 1);   // col
        }
        if (t == 0) g_done = 0;                // reset for next graph replay
    }
}

extern "C" void kernel_launch(void* const* d_in, const int* in_sizes, int n_in,
                              void* d_out, int out_size) {
    const float* x = (const float*)d_in[0];
    float* out = (float*)d_out;
    region_selector_fused<<<2048, 256>>>(x, out);
}